// round 7
// baseline (speedup 1.0000x reference)
#include <cuda_runtime.h>
#include <cuda_fp16.h>

#define Bq 512
#define Tq 128
#define Eq 256
#define Dq 256
#define G4 1024
#define BT (Bq*Tq)
#define NBLK 592
#define NLEAF 16
#define PER_LEAF 37   // 592 = 16*37

// ---------------- static device scratch ----------------
__device__ __half g_pre[(size_t)BT * Eq];     // enc @ W1_enc + b1 (fp16, 32MB)
__device__ float g_encfc[BT];                 // enc[b,t,:] . fc_w[0:256]
__device__ float g_whhT[Dq * G4];             // w_hh transposed [k][gate*256+d]
__device__ float g_bsum[G4];
__device__ float g_h[Bq * Dq];
__device__ float g_c[Bq * Dq];
__device__ float g_hp[16 * Bq * Eq];          // 16 K-partials of [h|c]@W1_hc
__device__ float g_gp[4 * (size_t)Bq * G4];   // 4 K-partials of h@w_hhT
__device__ unsigned g_cnt[NLEAF * 32];
__device__ unsigned g_master;
__device__ volatile unsigned g_gen;
__device__ unsigned g_qhp, g_qgp;             // per-step work queues

struct SmG { float As[16][68]; float Bs[16][68]; };      // 128-thread gemm tile
struct SmB {
    float hp[256]; float sc[128]; float ctxp[8][256];
    float ctx[256]; float red[16]; float misc[4];
};
struct SmP { float As[16][136]; float Bs[16][68]; };     // 256-thread prepass gemm
struct Sm {
    SmG g1;                          // gang1 (gp gemm)
    union { SmG g0; SmB b; } u;      // gang0: gemm then attention
    unsigned q0, q1;
};

__device__ __forceinline__ void bar_g(int id) {
    asm volatile("bar.sync %0, 128;" :: "r"(id));
}
__device__ __forceinline__ float tanh_approx(float x) {
    float y; asm("tanh.approx.f32 %0, %1;" : "=f"(y) : "f"(x)); return y;
}
__device__ __forceinline__ float sigmoid_f(float x) {
    return __fdividef(1.0f, 1.0f + __expf(-x));
}

// 64x64 tile GEMM, 128 threads (gang), 8x4 microtile, K multiple of 16.
__device__ __forceinline__ void gemm64x64_g(SmG* s, int g, int barid,
        const float* __restrict__ A, int lda,
        const float* __restrict__ Bm, int ldb,
        float* __restrict__ C, int ldc, int K)
{
    const int arow = g >> 1, ac = (g & 1) * 8;
    const int bk = g >> 3, bn = (g & 7) * 8;
    const int ty = g >> 4, tx = g & 15;

    float acc[8][4];
#pragma unroll
    for (int i = 0; i < 8; i++)
#pragma unroll
        for (int j = 0; j < 4; j++) acc[i][j] = 0.f;

    for (int k0 = 0; k0 < K; k0 += 16) {
        float4 a0 = __ldcg((const float4*)(A + (size_t)arow * lda + k0 + ac));
        float4 a1 = __ldcg((const float4*)(A + (size_t)arow * lda + k0 + ac + 4));
        float4 b0 = __ldcg((const float4*)(Bm + (size_t)(k0 + bk) * ldb + bn));
        float4 b1 = __ldcg((const float4*)(Bm + (size_t)(k0 + bk) * ldb + bn + 4));
        s->As[ac + 0][arow] = a0.x; s->As[ac + 1][arow] = a0.y;
        s->As[ac + 2][arow] = a0.z; s->As[ac + 3][arow] = a0.w;
        s->As[ac + 4][arow] = a1.x; s->As[ac + 5][arow] = a1.y;
        s->As[ac + 6][arow] = a1.z; s->As[ac + 7][arow] = a1.w;
        *(float4*)&s->Bs[bk][bn] = b0;
        *(float4*)&s->Bs[bk][bn + 4] = b1;
        bar_g(barid);
#pragma unroll
        for (int k = 0; k < 16; k++) {
            float4 q0 = *(const float4*)&s->As[k][ty * 8];
            float4 q1 = *(const float4*)&s->As[k][ty * 8 + 4];
            float4 bb = *(const float4*)&s->Bs[k][tx * 4];
            float av[8] = {q0.x, q0.y, q0.z, q0.w, q1.x, q1.y, q1.z, q1.w};
            float bv[4] = {bb.x, bb.y, bb.z, bb.w};
#pragma unroll
            for (int i = 0; i < 8; i++)
#pragma unroll
                for (int j = 0; j < 4; j++)
                    acc[i][j] = fmaf(av[i], bv[j], acc[i][j]);
        }
        bar_g(barid);
    }
#pragma unroll
    for (int i = 0; i < 8; i++)
        *(float4*)(C + (size_t)(ty * 8 + i) * ldc + tx * 4) =
            make_float4(acc[i][0], acc[i][1], acc[i][2], acc[i][3]);
}

// grid barrier core — called by tid 0 only (after a block-level sync+fence)
__device__ __forceinline__ void gbar_core(bool do_reset) {
    unsigned gen = g_gen;
    unsigned leaf = (blockIdx.x & (NLEAF - 1)) * 32;
    unsigned v = atomicAdd(&g_cnt[leaf], 1u) + 1u;
    if (v == (gen + 1u) * PER_LEAF) {
        unsigned m = atomicAdd(&g_master, 1u) + 1u;
        if (m == (gen + 1u) * NLEAF) {
            if (do_reset) { g_qhp = 0u; g_qgp = 0u; }
            __threadfence();
            g_gen = gen + 1u;
        } else {
            while (g_gen == gen) __nanosleep(32);
        }
    } else {
        while (g_gen == gen) __nanosleep(64);
    }
    __threadfence();
}

__global__ void __launch_bounds__(256, 4) decoder_persist(
        const float* __restrict__ enc, const float* __restrict__ yhist,
        const float* __restrict__ attn_w1, const float* __restrict__ attn_w2,
        const float* __restrict__ w_ih,
        const float* __restrict__ fc_w, const float* __restrict__ fc_b,
        const float* __restrict__ fcf_w, const float* __restrict__ fcf_b,
        float* __restrict__ out)
{
    __shared__ Sm sm;
    const int bid = blockIdx.x;
    const int tid = threadIdx.x;
    const int lane = tid & 31, warp = tid >> 5;
    const int b = bid;
    const bool hasrow = (b < Bq);

    for (int t = 0; t < Tq; t++) {
        if (tid >= 128) {
            // ================= gang 1: gp GEMM units (runs through barrier A) =====
            const int g = tid - 128;
            for (;;) {
                if (g == 0) sm.q1 = atomicAdd(&g_qgp, 1u);
                bar_g(3);
                unsigned u = sm.q1;
                bar_g(3);
                if (u >= 512u) break;
                int kq = u & 3; int tile = u >> 2;
                int mt = tile >> 4, nt = tile & 15;
                gemm64x64_g(&sm.g1, g, 3,
                    g_h + (size_t)mt * 64 * Dq + kq * 64, Dq,
                    g_whhT + (size_t)(kq * 64) * G4 + nt * 64, G4,
                    g_gp + (size_t)kq * (Bq * G4) + (size_t)mt * 64 * G4 + nt * 64,
                    G4, 64);
            }
        } else {
            // ================= gang 0: hp GEMM units, partial gridbar, attention ==
            const int g = tid;
            for (;;) {
                if (g == 0) sm.q0 = atomicAdd(&g_qhp, 1u);
                bar_g(1);
                unsigned u = sm.q0;
                bar_g(1);
                if (u >= 512u) break;
                int kq = u & 15; int tile = u >> 4;
                int mt = tile >> 2, nt = tile & 3;
                const float* A = (kq < 8 ? g_h + kq * 32 : g_c + (kq - 8) * 32)
                                 + (size_t)mt * 64 * Dq;
                gemm64x64_g(&sm.u.g0, g, 1, A, Dq,
                    attn_w1 + (size_t)(kq * 32) * Eq + nt * 64, Eq,
                    g_hp + (size_t)kq * (Bq * Eq) + (size_t)mt * 64 * Eq + nt * 64,
                    Eq, 32);
            }
            // ---- partial grid barrier A: hp complete (gang0 only waits) ----
            __threadfence();
            bar_g(1);
            if (tid == 0) gbar_core(false);
            bar_g(1);

            if (hasrow) {
                // ---- attention for row b, 4 warps ----
                float h0 = 0.f, h1 = 0.f;
#pragma unroll
                for (int q = 0; q < 16; q++) {
                    h0 += __ldcg(&g_hp[(size_t)q * (Bq * Eq) + b * Eq + tid]);
                    h1 += __ldcg(&g_hp[(size_t)q * (Bq * Eq) + b * Eq + 128 + tid]);
                }
                sm.u.b.hp[tid] = h0; sm.u.b.hp[tid + 128] = h1;
                bar_g(1);

                float hpr[8], w2r[8];
#pragma unroll
                for (int j = 0; j < 8; j++) {
                    hpr[j] = sm.u.b.hp[lane * 8 + j];
                    w2r[j] = attn_w2[lane * 8 + j];
                }
                const uint4* preb = (const uint4*)(g_pre + (size_t)b * Tq * Eq);
#pragma unroll
                for (int i = 0; i < 8; i++) {
                    uint4 pv[4];
#pragma unroll
                    for (int j = 0; j < 4; j++)
                        pv[j] = __ldcg(preb + (size_t)(warp + 4 * (i * 4 + j)) * 32 + lane);
#pragma unroll
                    for (int j = 0; j < 4; j++) {
                        const __half2* ph = (const __half2*)&pv[j];
                        float a = 0.f;
#pragma unroll
                        for (int q = 0; q < 4; q++) {
                            float2 f = __half22float2(ph[q]);
                            a = fmaf(w2r[2 * q],     tanh_approx(hpr[2 * q]     + f.x), a);
                            a = fmaf(w2r[2 * q + 1], tanh_approx(hpr[2 * q + 1] + f.y), a);
                        }
#pragma unroll
                        for (int o = 16; o; o >>= 1) a += __shfl_xor_sync(0xffffffffu, a, o);
                        if (lane == 0) sm.u.b.sc[warp + 4 * (i * 4 + j)] = a;
                    }
                }
                bar_g(1);

                // softmax over T=128 (attn_b2 dropped: shift-invariant)
                float sv = sm.u.b.sc[tid];
                float mx = sv;
#pragma unroll
                for (int o = 16; o; o >>= 1) mx = fmaxf(mx, __shfl_xor_sync(0xffffffffu, mx, o));
                if (lane == 0) sm.u.b.red[warp] = mx;
                bar_g(1);
                float mm = fmaxf(fmaxf(sm.u.b.red[0], sm.u.b.red[1]),
                                 fmaxf(sm.u.b.red[2], sm.u.b.red[3]));
                float ex = __expf(sv - mm);
                float ss = ex;
#pragma unroll
                for (int o = 16; o; o >>= 1) ss += __shfl_xor_sync(0xffffffffu, ss, o);
                float yd = ex * __ldcg(&g_encfc[b * Tq + tid]);
#pragma unroll
                for (int o = 16; o; o >>= 1) yd += __shfl_xor_sync(0xffffffffu, yd, o);
                if (lane == 0) { sm.u.b.red[4 + warp] = ss; sm.u.b.red[8 + warp] = yd; }
                sm.u.b.sc[tid] = ex;
                bar_g(1);
                if (tid == 0) {
                    float tot = sm.u.b.red[4] + sm.u.b.red[5] + sm.u.b.red[6] + sm.u.b.red[7];
                    float invs = __fdividef(1.0f, tot);
                    sm.u.b.misc[1] = invs;
                    sm.u.b.misc[2] = (sm.u.b.red[8] + sm.u.b.red[9] + sm.u.b.red[10]
                                      + sm.u.b.red[11]) * invs
                                     + yhist[b * Tq + t] * fc_w[256] + fc_b[0];
                }
            }
        }

        // ============ grid barrier B: gp + attention complete ============
        __threadfence();
        __syncthreads();
        if (tid == 0) gbar_core(false);
        __syncthreads();

        // ============ epilogue for row b (all 256 threads) ============
        if (hasrow) {
            if (t == Tq - 1) {
                // full ctx (needed only for fc_final)
                float invs = sm.u.b.misc[1];
                float a8[8] = {0.f, 0.f, 0.f, 0.f, 0.f, 0.f, 0.f, 0.f};
                const float4* encb = (const float4*)(enc + (size_t)b * Tq * Eq);
#pragma unroll 2
                for (int i = 0; i < 16; i++) {
                    int tt = (warp << 4) + i;
                    float wgt = sm.u.b.sc[tt];
                    float4 e0 = __ldcg(encb + (size_t)tt * 64 + lane * 2);
                    float4 e1 = __ldcg(encb + (size_t)tt * 64 + lane * 2 + 1);
                    a8[0] = fmaf(wgt, e0.x, a8[0]); a8[1] = fmaf(wgt, e0.y, a8[1]);
                    a8[2] = fmaf(wgt, e0.z, a8[2]); a8[3] = fmaf(wgt, e0.w, a8[3]);
                    a8[4] = fmaf(wgt, e1.x, a8[4]); a8[5] = fmaf(wgt, e1.y, a8[5]);
                    a8[6] = fmaf(wgt, e1.z, a8[6]); a8[7] = fmaf(wgt, e1.w, a8[7]);
                }
#pragma unroll
                for (int j = 0; j < 8; j++) sm.u.b.ctxp[warp][lane * 8 + j] = a8[j];
                __syncthreads();
                float cv = 0.f;
#pragma unroll
                for (int w = 0; w < 8; w++) cv += sm.u.b.ctxp[w][tid];
                sm.u.b.ctx[tid] = cv * invs;
                __syncthreads();
            }

            float yt = sm.u.b.misc[2];
            int d = tid;
            float gv[4];
#pragma unroll
            for (int g = 0; g < 4; g++) {
                float a = fmaf(yt, w_ih[g * 256 + d], g_bsum[g * 256 + d]);
#pragma unroll
                for (int kq = 0; kq < 4; kq++)
                    a += __ldcg(&g_gp[(size_t)kq * (Bq * G4) + (size_t)b * G4 + g * 256 + d]);
                gv[g] = a;
            }
            float cprev = g_c[b * Dq + d];
            float cn = sigmoid_f(gv[1]) * cprev + sigmoid_f(gv[0]) * tanhf(gv[2]);
            float hn = sigmoid_f(gv[3]) * tanhf(cn);
            g_c[b * Dq + d] = cn;
            g_h[b * Dq + d] = hn;

            if (t == Tq - 1) {
                float q = hn * fcf_w[d] + sm.u.b.ctx[d] * fcf_w[Dq + d];
#pragma unroll
                for (int o = 16; o; o >>= 1) q += __shfl_xor_sync(0xffffffffu, q, o);
                __syncthreads();
                if (lane == 0) sm.u.b.red[warp] = q;
                __syncthreads();
                if (tid == 0) {
                    float tot = 0.f;
#pragma unroll
                    for (int w = 0; w < 8; w++) tot += sm.u.b.red[w];
                    out[b] = tot + fcf_b[0];
                }
            }
        }

        // ============ grid barrier C: h,c updated; reset queues ============
        __threadfence();
        __syncthreads();
        if (tid == 0) gbar_core(true);
        __syncthreads();
    }
}

// 256-thread 128x64 GEMM for the prepass (R6 engine)
template<typename TO>
__device__ __forceinline__ void gemm128x64(SmP* s,
        const float* __restrict__ A, int lda,
        const float* __restrict__ Bm, int ldb,
        TO* __restrict__ C, int ldc, int K,
        const float* __restrict__ bias)
{
    const int tid = threadIdx.x;
    const int ty = tid >> 4, tx = tid & 15;
    const int arow = tid >> 2, ac4 = (tid & 3) << 2;
    const int bk = tid >> 4, bc4 = (tid & 15) << 2;

    float acc[8][4];
#pragma unroll
    for (int i = 0; i < 8; i++)
#pragma unroll
        for (int j = 0; j < 4; j++) acc[i][j] = 0.f;

    for (int k0 = 0; k0 < K; k0 += 16) {
        float4 av0 = __ldcg((const float4*)(A + (size_t)arow * lda + k0 + ac4));
        float4 av1 = __ldcg((const float4*)(A + (size_t)(arow + 64) * lda + k0 + ac4));
        float4 bv  = __ldcg((const float4*)(Bm + (size_t)(k0 + bk) * ldb + bc4));
        s->As[ac4 + 0][arow] = av0.x; s->As[ac4 + 1][arow] = av0.y;
        s->As[ac4 + 2][arow] = av0.z; s->As[ac4 + 3][arow] = av0.w;
        s->As[ac4 + 0][arow + 64] = av1.x; s->As[ac4 + 1][arow + 64] = av1.y;
        s->As[ac4 + 2][arow + 64] = av1.z; s->As[ac4 + 3][arow + 64] = av1.w;
        *(float4*)&s->Bs[bk][bc4] = bv;
        __syncthreads();
#pragma unroll
        for (int k = 0; k < 16; k++) {
            float4 a0 = *(const float4*)&s->As[k][ty << 3];
            float4 a1 = *(const float4*)&s->As[k][(ty << 3) + 4];
            float4 b4 = *(const float4*)&s->Bs[k][tx << 2];
            float av[8] = {a0.x, a0.y, a0.z, a0.w, a1.x, a1.y, a1.z, a1.w};
            float bb[4] = {b4.x, b4.y, b4.z, b4.w};
#pragma unroll
            for (int i = 0; i < 8; i++)
#pragma unroll
                for (int j = 0; j < 4; j++)
                    acc[i][j] = fmaf(av[i], bb[j], acc[i][j]);
        }
        __syncthreads();
    }
#pragma unroll
    for (int i = 0; i < 8; i++) {
        float v0 = acc[i][0], v1 = acc[i][1], v2 = acc[i][2], v3 = acc[i][3];
        if (bias) {
            v0 += bias[(tx << 2) + 0]; v1 += bias[(tx << 2) + 1];
            v2 += bias[(tx << 2) + 2]; v3 += bias[(tx << 2) + 3];
        }
        size_t off = (size_t)((ty << 3) + i) * ldc + (tx << 2);
        if constexpr (sizeof(TO) == 2) {
            __half2 h0 = __floats2half2_rn(v0, v1);
            __half2 h1 = __floats2half2_rn(v2, v3);
            uint2 u; u.x = *(unsigned*)&h0; u.y = *(unsigned*)&h1;
            *(uint2*)((__half*)C + off) = u;
        } else {
            *(float4*)((float*)C + off) = make_float4(v0, v1, v2, v3);
        }
    }
}

__global__ void prep_kernel(const float* __restrict__ w_hh,
                            const float* __restrict__ b_ih,
                            const float* __restrict__ b_hh)
{
    int i = blockIdx.x * blockDim.x + threadIdx.x;
    if (i < G4 * Dq) {
        int j = i >> 8, k = i & 255;
        g_whhT[(size_t)k * G4 + j] = w_hh[i];
    }
    if (i < G4) g_bsum[i] = b_ih[i] + b_hh[i];
    if (i < Bq * Dq) { g_h[i] = 0.f; g_c[i] = 0.f; }
    if (i < NLEAF * 32) g_cnt[i] = 0u;
    if (i == 0) { g_master = 0u; g_gen = 0u; g_qhp = 0u; g_qgp = 0u; }
}

// encfc[b,t] = enc[b,t,:] . fc_w[0:256]   (one warp per (b,t))
__global__ void __launch_bounds__(256) encfc_kernel(
        const float* __restrict__ enc, const float* __restrict__ fc_w)
{
    int w = blockIdx.x * 8 + (threadIdx.x >> 5);
    int lane = threadIdx.x & 31;
    const float4* p = (const float4*)(enc + (size_t)w * Eq);
    const float4* q = (const float4*)fc_w;
    float s = 0.f;
#pragma unroll
    for (int j = 0; j < 2; j++) {
        float4 e = __ldcg(p + lane + 32 * j);
        float4 f = __ldg(q + lane + 32 * j);
        s += e.x * f.x + e.y * f.y + e.z * f.z + e.w * f.w;
    }
#pragma unroll
    for (int o = 16; o; o >>= 1) s += __shfl_xor_sync(0xffffffffu, s, o);
    if (lane == 0) g_encfc[w] = s;
}

__global__ void __launch_bounds__(256) pre_gemm_kernel(
        const float* __restrict__ enc, const float* __restrict__ attn_w1,
        const float* __restrict__ attn_b1)
{
    __shared__ SmP sa;
    int mt = blockIdx.x >> 2, nt = blockIdx.x & 3;
    gemm128x64<__half>(&sa,
        enc + (size_t)mt * 128 * Eq, Eq,
        attn_w1 + (size_t)(2 * Dq) * Eq + nt * 64, Eq,
        g_pre + (size_t)mt * 128 * Eq + nt * 64, Eq, 256,
        attn_b1 + nt * 64);
}

extern "C" void kernel_launch(void* const* d_in, const int* in_sizes, int n_in,
                              void* d_out, int out_size)
{
    const float* enc     = (const float*)d_in[0];
    const float* yhist   = (const float*)d_in[1];
    const float* attn_w1 = (const float*)d_in[2];
    const float* attn_b1 = (const float*)d_in[3];
    const float* attn_w2 = (const float*)d_in[4];
    // d_in[5] = attn_b2: unused (softmax is shift-invariant)
    const float* w_ih    = (const float*)d_in[6];
    const float* w_hh    = (const float*)d_in[7];
    const float* b_ih    = (const float*)d_in[8];
    const float* b_hh    = (const float*)d_in[9];
    const float* fc_w    = (const float*)d_in[10];
    const float* fc_b    = (const float*)d_in[11];
    const float* fcf_w   = (const float*)d_in[12];
    const float* fcf_b   = (const float*)d_in[13];
    float* out = (float*)d_out;

    prep_kernel<<<1024, 256>>>(w_hh, b_ih, b_hh);
    encfc_kernel<<<BT / 8, 256>>>(enc, fc_w);
    pre_gemm_kernel<<<2048, 256>>>(enc, attn_w1, attn_b1);
    decoder_persist<<<NBLK, 256>>>(enc, yhist, attn_w1, attn_w2, w_ih,
                                   fc_w, fc_b, fcf_w, fcf_b, out);
}

// round 8
// speedup vs baseline: 1.0536x; 1.0536x over previous
#include <cuda_runtime.h>
#include <cuda_fp16.h>

#define Bq 512
#define Tq 128
#define Eq 256
#define Dq 256
#define G4 1024
#define BT (Bq*Tq)
#define NBLK 512
#define NLEAF 16
#define PER_LEAF 32   // 512 = 16*32

// ---------------- static device scratch ----------------
__device__ __half g_pre[(size_t)BT * Eq];     // enc @ W1_enc + b1 (fp16, 32MB) — immutable in persist
__device__ float g_encfc[BT];                 // enc[b,t,:] . fc_w[0:256] — immutable
__device__ float g_whhT[Dq * G4];             // w_hh transposed — immutable
__device__ float g_bsum[G4];
__device__ float g_h[Bq * Dq];                // mutable
__device__ float g_c[Bq * Dq];                // mutable
__device__ float g_hp[16 * Bq * Eq];          // mutable (16 K-partials of [h|c]@W1_hc)
__device__ float g_gp[4 * (size_t)Bq * G4];   // mutable (4 K-partials of h@w_hhT)
__device__ unsigned g_cnt[NLEAF * 32];
__device__ unsigned g_master;
__device__ volatile unsigned g_gen;

struct SmG { float As[16][68]; float Bs[16][68]; };      // 128-thread gemm tile
struct SmB {
    float hp[256]; float sc[128]; float ctxp[8][256];
    float ctx[256]; float red[16]; float misc[4];
};
struct SmP { float As[16][136]; float Bs[16][68]; };     // 256-thread prepass gemm
struct Sm {
    SmG g1;                          // gang1 (gp gemm)
    union { SmG g0; SmB b; } u;      // gang0: gemm then attention
};

__device__ __forceinline__ void bar_g(int id) {
    asm volatile("bar.sync %0, 128;" :: "r"(id));
}
__device__ __forceinline__ float tanh_approx(float x) {
    float y; asm("tanh.approx.f32 %0, %1;" : "=f"(y) : "f"(x)); return y;
}
__device__ __forceinline__ float sigmoid_f(float x) {
    return __fdividef(1.0f, 1.0f + __expf(-x));
}

// 64x64 tile GEMM, 128 threads (gang), 8x4 microtile, K multiple of 16.
// A: mutable (h/c) -> __ldcg (L1 bypass). B: immutable weights -> __ldg (L1 cached).
__device__ __forceinline__ void gemm64x64_g(SmG* s, int g, int barid,
        const float* __restrict__ A, int lda,
        const float* __restrict__ Bm, int ldb,
        float* __restrict__ C, int ldc, int K)
{
    const int arow = g >> 1, ac = (g & 1) * 8;
    const int bk = g >> 3, bn = (g & 7) * 8;
    const int ty = g >> 4, tx = g & 15;

    float acc[8][4];
#pragma unroll
    for (int i = 0; i < 8; i++)
#pragma unroll
        for (int j = 0; j < 4; j++) acc[i][j] = 0.f;

    for (int k0 = 0; k0 < K; k0 += 16) {
        float4 a0 = __ldcg((const float4*)(A + (size_t)arow * lda + k0 + ac));
        float4 a1 = __ldcg((const float4*)(A + (size_t)arow * lda + k0 + ac + 4));
        float4 b0 = __ldg((const float4*)(Bm + (size_t)(k0 + bk) * ldb + bn));
        float4 b1 = __ldg((const float4*)(Bm + (size_t)(k0 + bk) * ldb + bn + 4));
        s->As[ac + 0][arow] = a0.x; s->As[ac + 1][arow] = a0.y;
        s->As[ac + 2][arow] = a0.z; s->As[ac + 3][arow] = a0.w;
        s->As[ac + 4][arow] = a1.x; s->As[ac + 5][arow] = a1.y;
        s->As[ac + 6][arow] = a1.z; s->As[ac + 7][arow] = a1.w;
        *(float4*)&s->Bs[bk][bn] = b0;
        *(float4*)&s->Bs[bk][bn + 4] = b1;
        bar_g(barid);
#pragma unroll
        for (int k = 0; k < 16; k++) {
            float4 q0 = *(const float4*)&s->As[k][ty * 8];
            float4 q1 = *(const float4*)&s->As[k][ty * 8 + 4];
            float4 bb = *(const float4*)&s->Bs[k][tx * 4];
            float av[8] = {q0.x, q0.y, q0.z, q0.w, q1.x, q1.y, q1.z, q1.w};
            float bv[4] = {bb.x, bb.y, bb.z, bb.w};
#pragma unroll
            for (int i = 0; i < 8; i++)
#pragma unroll
                for (int j = 0; j < 4; j++)
                    acc[i][j] = fmaf(av[i], bv[j], acc[i][j]);
        }
        bar_g(barid);
    }
#pragma unroll
    for (int i = 0; i < 8; i++)
        *(float4*)(C + (size_t)(ty * 8 + i) * ldc + tx * 4) =
            make_float4(acc[i][0], acc[i][1], acc[i][2], acc[i][3]);
}

// grid barrier core — called by tid 0 only (after a block/gang-level sync+fence)
__device__ __forceinline__ void gbar_core() {
    unsigned gen = g_gen;
    unsigned leaf = (blockIdx.x & (NLEAF - 1)) * 32;
    unsigned v = atomicAdd(&g_cnt[leaf], 1u) + 1u;
    if (v == (gen + 1u) * PER_LEAF) {
        unsigned m = atomicAdd(&g_master, 1u) + 1u;
        if (m == (gen + 1u) * NLEAF) {
            __threadfence();
            g_gen = gen + 1u;
        } else {
            while (g_gen == gen) __nanosleep(32);
        }
    } else {
        while (g_gen == gen) __nanosleep(64);
    }
    __threadfence();
}

__global__ void __launch_bounds__(256, 4) decoder_persist(
        const float* __restrict__ enc, const float* __restrict__ yhist,
        const float* __restrict__ attn_w1, const float* __restrict__ attn_w2,
        const float* __restrict__ w_ih,
        const float* __restrict__ fc_w, const float* __restrict__ fc_b,
        const float* __restrict__ fcf_w, const float* __restrict__ fcf_b,
        float* __restrict__ out)
{
    __shared__ Sm sm;
    const int bid = blockIdx.x;
    const int tid = threadIdx.x;
    const int lane = tid & 31, warp = tid >> 5;
    const int b = bid;

    for (int t = 0; t < Tq; t++) {
        if (tid >= 128) {
            // ===== gang 1: static gp unit (overlaps gang0's barrier-A + attention) =====
            const int g = tid - 128;
            int kq = bid & 3, tile = bid >> 2;
            int mt = tile >> 4, nt = tile & 15;
            gemm64x64_g(&sm.g1, g, 3,
                g_h + (size_t)mt * 64 * Dq + kq * 64, Dq,
                g_whhT + (size_t)(kq * 64) * G4 + nt * 64, G4,
                g_gp + (size_t)kq * (Bq * G4) + (size_t)mt * 64 * G4 + nt * 64,
                G4, 64);
            __threadfence();
        } else {
            // ===== gang 0: static hp unit, partial grid barrier, attention =====
            const int g = tid;
            {
                int kq = bid & 15, tile = bid >> 4;
                int mt = tile >> 2, nt = tile & 3;
                const float* A = (kq < 8 ? g_h + kq * 32 : g_c + (kq - 8) * 32)
                                 + (size_t)mt * 64 * Dq;
                gemm64x64_g(&sm.u.g0, g, 1, A, Dq,
                    attn_w1 + (size_t)(kq * 32) * Eq + nt * 64, Eq,
                    g_hp + (size_t)kq * (Bq * Eq) + (size_t)mt * 64 * Eq + nt * 64,
                    Eq, 32);
            }
            // ---- grid barrier A: hp complete (only gang0 waits) ----
            __threadfence();
            bar_g(1);
            if (tid == 0) gbar_core();
            bar_g(1);

            // ---- attention for row b, 4 warps ----
            float h0 = 0.f, h1 = 0.f;
#pragma unroll
            for (int q = 0; q < 16; q++) {
                h0 += __ldcg(&g_hp[(size_t)q * (Bq * Eq) + b * Eq + tid]);
                h1 += __ldcg(&g_hp[(size_t)q * (Bq * Eq) + b * Eq + 128 + tid]);
            }
            sm.u.b.hp[tid] = h0; sm.u.b.hp[tid + 128] = h1;
            bar_g(1);

            float hpr[8], w2r[8];
#pragma unroll
            for (int j = 0; j < 8; j++) {
                hpr[j] = sm.u.b.hp[lane * 8 + j];
                w2r[j] = __ldg(&attn_w2[lane * 8 + j]);
            }
            const uint4* preb = (const uint4*)(g_pre + (size_t)b * Tq * Eq);
#pragma unroll
            for (int i = 0; i < 8; i++) {
                uint4 pv[4];
#pragma unroll
                for (int j = 0; j < 4; j++)
                    pv[j] = __ldg(preb + (size_t)(warp + 4 * (i * 4 + j)) * 32 + lane);
#pragma unroll
                for (int j = 0; j < 4; j++) {
                    const __half2* ph = (const __half2*)&pv[j];
                    float a = 0.f;
#pragma unroll
                    for (int q = 0; q < 4; q++) {
                        float2 f = __half22float2(ph[q]);
                        a = fmaf(w2r[2 * q],     tanh_approx(hpr[2 * q]     + f.x), a);
                        a = fmaf(w2r[2 * q + 1], tanh_approx(hpr[2 * q + 1] + f.y), a);
                    }
#pragma unroll
                    for (int o = 16; o; o >>= 1) a += __shfl_xor_sync(0xffffffffu, a, o);
                    if (lane == 0) sm.u.b.sc[warp + 4 * (i * 4 + j)] = a;
                }
            }
            bar_g(1);

            // softmax over T=128 (attn_b2 dropped: shift-invariant)
            float sv = sm.u.b.sc[tid];
            float mx = sv;
#pragma unroll
            for (int o = 16; o; o >>= 1) mx = fmaxf(mx, __shfl_xor_sync(0xffffffffu, mx, o));
            if (lane == 0) sm.u.b.red[warp] = mx;
            bar_g(1);
            float mm = fmaxf(fmaxf(sm.u.b.red[0], sm.u.b.red[1]),
                             fmaxf(sm.u.b.red[2], sm.u.b.red[3]));
            float ex = __expf(sv - mm);
            float ss = ex;
#pragma unroll
            for (int o = 16; o; o >>= 1) ss += __shfl_xor_sync(0xffffffffu, ss, o);
            float yd = ex * __ldg(&g_encfc[b * Tq + tid]);
#pragma unroll
            for (int o = 16; o; o >>= 1) yd += __shfl_xor_sync(0xffffffffu, yd, o);
            if (lane == 0) { sm.u.b.red[4 + warp] = ss; sm.u.b.red[8 + warp] = yd; }
            sm.u.b.sc[tid] = ex;
            bar_g(1);
            if (tid == 0) {
                float tot = sm.u.b.red[4] + sm.u.b.red[5] + sm.u.b.red[6] + sm.u.b.red[7];
                float invs = __fdividef(1.0f, tot);
                sm.u.b.misc[1] = invs;
                sm.u.b.misc[2] = (sm.u.b.red[8] + sm.u.b.red[9] + sm.u.b.red[10]
                                  + sm.u.b.red[11]) * invs
                                 + __ldg(&yhist[b * Tq + t]) * fc_w[256] + fc_b[0];
            }
        }

        // ============ grid barrier B: gp + attention complete ============
        __syncthreads();
        if (tid == 0) gbar_core();
        __syncthreads();

        // ============ epilogue for row b (all 256 threads) ============
        {
            if (t == Tq - 1) {
                // full ctx (needed only for fc_final)
                float invs = sm.u.b.misc[1];
                float a8[8] = {0.f, 0.f, 0.f, 0.f, 0.f, 0.f, 0.f, 0.f};
                const float4* encb = (const float4*)(enc + (size_t)b * Tq * Eq);
#pragma unroll 2
                for (int i = 0; i < 16; i++) {
                    int tt = (warp << 4) + i;
                    float wgt = sm.u.b.sc[tt];
                    float4 e0 = __ldg(encb + (size_t)tt * 64 + lane * 2);
                    float4 e1 = __ldg(encb + (size_t)tt * 64 + lane * 2 + 1);
                    a8[0] = fmaf(wgt, e0.x, a8[0]); a8[1] = fmaf(wgt, e0.y, a8[1]);
                    a8[2] = fmaf(wgt, e0.z, a8[2]); a8[3] = fmaf(wgt, e0.w, a8[3]);
                    a8[4] = fmaf(wgt, e1.x, a8[4]); a8[5] = fmaf(wgt, e1.y, a8[5]);
                    a8[6] = fmaf(wgt, e1.z, a8[6]); a8[7] = fmaf(wgt, e1.w, a8[7]);
                }
#pragma unroll
                for (int j = 0; j < 8; j++) sm.u.b.ctxp[warp][lane * 8 + j] = a8[j];
                __syncthreads();
                float cv = 0.f;
#pragma unroll
                for (int w = 0; w < 8; w++) cv += sm.u.b.ctxp[w][tid];
                sm.u.b.ctx[tid] = cv * invs;
                __syncthreads();
            }

            float yt = sm.u.b.misc[2];
            int d = tid;
            float gv[4];
#pragma unroll
            for (int g = 0; g < 4; g++) {
                float a = fmaf(yt, __ldg(&w_ih[g * 256 + d]), g_bsum[g * 256 + d]);
#pragma unroll
                for (int kq = 0; kq < 4; kq++)
                    a += __ldcg(&g_gp[(size_t)kq * (Bq * G4) + (size_t)b * G4 + g * 256 + d]);
                gv[g] = a;
            }
            float cprev = __ldcg(&g_c[b * Dq + d]);
            float cn = sigmoid_f(gv[1]) * cprev + sigmoid_f(gv[0]) * tanhf(gv[2]);
            float hn = sigmoid_f(gv[3]) * tanhf(cn);
            g_c[b * Dq + d] = cn;
            g_h[b * Dq + d] = hn;

            if (t == Tq - 1) {
                float q = hn * __ldg(&fcf_w[d]) + sm.u.b.ctx[d] * __ldg(&fcf_w[Dq + d]);
#pragma unroll
                for (int o = 16; o; o >>= 1) q += __shfl_xor_sync(0xffffffffu, q, o);
                __syncthreads();
                if (lane == 0) sm.u.b.red[warp] = q;
                __syncthreads();
                if (tid == 0) {
                    float tot = 0.f;
#pragma unroll
                    for (int w = 0; w < 8; w++) tot += sm.u.b.red[w];
                    out[b] = tot + fcf_b[0];
                }
            }
        }

        // ============ grid barrier C: h,c updated ============
        __threadfence();
        __syncthreads();
        if (tid == 0) gbar_core();
        __syncthreads();
    }
}

// 256-thread 128x64 GEMM for the prepass
template<typename TO>
__device__ __forceinline__ void gemm128x64(SmP* s,
        const float* __restrict__ A, int lda,
        const float* __restrict__ Bm, int ldb,
        TO* __restrict__ C, int ldc, int K,
        const float* __restrict__ bias)
{
    const int tid = threadIdx.x;
    const int ty = tid >> 4, tx = tid & 15;
    const int arow = tid >> 2, ac4 = (tid & 3) << 2;
    const int bk = tid >> 4, bc4 = (tid & 15) << 2;

    float acc[8][4];
#pragma unroll
    for (int i = 0; i < 8; i++)
#pragma unroll
        for (int j = 0; j < 4; j++) acc[i][j] = 0.f;

    for (int k0 = 0; k0 < K; k0 += 16) {
        float4 av0 = __ldcg((const float4*)(A + (size_t)arow * lda + k0 + ac4));
        float4 av1 = __ldcg((const float4*)(A + (size_t)(arow + 64) * lda + k0 + ac4));
        float4 bv  = __ldg((const float4*)(Bm + (size_t)(k0 + bk) * ldb + bc4));
        s->As[ac4 + 0][arow] = av0.x; s->As[ac4 + 1][arow] = av0.y;
        s->As[ac4 + 2][arow] = av0.z; s->As[ac4 + 3][arow] = av0.w;
        s->As[ac4 + 0][arow + 64] = av1.x; s->As[ac4 + 1][arow + 64] = av1.y;
        s->As[ac4 + 2][arow + 64] = av1.z; s->As[ac4 + 3][arow + 64] = av1.w;
        *(float4*)&s->Bs[bk][bc4] = bv;
        __syncthreads();
#pragma unroll
        for (int k = 0; k < 16; k++) {
            float4 a0 = *(const float4*)&s->As[k][ty << 3];
            float4 a1 = *(const float4*)&s->As[k][(ty << 3) + 4];
            float4 b4 = *(const float4*)&s->Bs[k][tx << 2];
            float av[8] = {a0.x, a0.y, a0.z, a0.w, a1.x, a1.y, a1.z, a1.w};
            float bb[4] = {b4.x, b4.y, b4.z, b4.w};
#pragma unroll
            for (int i = 0; i < 8; i++)
#pragma unroll
                for (int j = 0; j < 4; j++)
                    acc[i][j] = fmaf(av[i], bb[j], acc[i][j]);
        }
        __syncthreads();
    }
#pragma unroll
    for (int i = 0; i < 8; i++) {
        float v0 = acc[i][0], v1 = acc[i][1], v2 = acc[i][2], v3 = acc[i][3];
        if (bias) {
            v0 += bias[(tx << 2) + 0]; v1 += bias[(tx << 2) + 1];
            v2 += bias[(tx << 2) + 2]; v3 += bias[(tx << 2) + 3];
        }
        size_t off = (size_t)((ty << 3) + i) * ldc + (tx << 2);
        if constexpr (sizeof(TO) == 2) {
            __half2 h0 = __floats2half2_rn(v0, v1);
            __half2 h1 = __floats2half2_rn(v2, v3);
            uint2 u; u.x = *(unsigned*)&h0; u.y = *(unsigned*)&h1;
            *(uint2*)((__half*)C + off) = u;
        } else {
            *(float4*)((float*)C + off) = make_float4(v0, v1, v2, v3);
        }
    }
}

__global__ void prep_kernel(const float* __restrict__ w_hh,
                            const float* __restrict__ b_ih,
                            const float* __restrict__ b_hh)
{
    int i = blockIdx.x * blockDim.x + threadIdx.x;
    if (i < G4 * Dq) {
        int j = i >> 8, k = i & 255;
        g_whhT[(size_t)k * G4 + j] = w_hh[i];
    }
    if (i < G4) g_bsum[i] = b_ih[i] + b_hh[i];
    if (i < Bq * Dq) { g_h[i] = 0.f; g_c[i] = 0.f; }
    if (i < NLEAF * 32) g_cnt[i] = 0u;
    if (i == 0) { g_master = 0u; g_gen = 0u; }
}

// encfc[b,t] = enc[b,t,:] . fc_w[0:256]   (one warp per (b,t))
__global__ void __launch_bounds__(256) encfc_kernel(
        const float* __restrict__ enc, const float* __restrict__ fc_w)
{
    int w = blockIdx.x * 8 + (threadIdx.x >> 5);
    int lane = threadIdx.x & 31;
    const float4* p = (const float4*)(enc + (size_t)w * Eq);
    const float4* q = (const float4*)fc_w;
    float s = 0.f;
#pragma unroll
    for (int j = 0; j < 2; j++) {
        float4 e = __ldcg(p + lane + 32 * j);
        float4 f = __ldg(q + lane + 32 * j);
        s += e.x * f.x + e.y * f.y + e.z * f.z + e.w * f.w;
    }
#pragma unroll
    for (int o = 16; o; o >>= 1) s += __shfl_xor_sync(0xffffffffu, s, o);
    if (lane == 0) g_encfc[w] = s;
}

__global__ void __launch_bounds__(256) pre_gemm_kernel(
        const float* __restrict__ enc, const float* __restrict__ attn_w1,
        const float* __restrict__ attn_b1)
{
    __shared__ SmP sa;
    int mt = blockIdx.x >> 2, nt = blockIdx.x & 3;
    gemm128x64<__half>(&sa,
        enc + (size_t)mt * 128 * Eq, Eq,
        attn_w1 + (size_t)(2 * Dq) * Eq + nt * 64, Eq,
        g_pre + (size_t)mt * 128 * Eq + nt * 64, Eq, 256,
        attn_b1 + nt * 64);
}

extern "C" void kernel_launch(void* const* d_in, const int* in_sizes, int n_in,
                              void* d_out, int out_size)
{
    const float* enc     = (const float*)d_in[0];
    const float* yhist   = (const float*)d_in[1];
    const float* attn_w1 = (const float*)d_in[2];
    const float* attn_b1 = (const float*)d_in[3];
    const float* attn_w2 = (const float*)d_in[4];
    // d_in[5] = attn_b2: unused (softmax is shift-invariant)
    const float* w_ih    = (const float*)d_in[6];
    const float* w_hh    = (const float*)d_in[7];
    const float* b_ih    = (const float*)d_in[8];
    const float* b_hh    = (const float*)d_in[9];
    const float* fc_w    = (const float*)d_in[10];
    const float* fc_b    = (const float*)d_in[11];
    const float* fcf_w   = (const float*)d_in[12];
    const float* fcf_b   = (const float*)d_in[13];
    float* out = (float*)d_out;

    prep_kernel<<<1024, 256>>>(w_hh, b_ih, b_hh);
    encfc_kernel<<<BT / 8, 256>>>(enc, fc_w);
    pre_gemm_kernel<<<2048, 256>>>(enc, attn_w1, attn_b1);
    decoder_persist<<<NBLK, 256>>>(enc, yhist, attn_w1, attn_w2, w_ih,
                                   fc_w, fc_b, fcf_w, fcf_b, out);
}